// round 1
// baseline (speedup 1.0000x reference)
#include <cuda_runtime.h>
#include <cstdint>

// Problem constants
#define H 4096
#define INF 4096
#define OUTF 4096
#define KRED 256          // reduced K dimension (TILE_H)
#define NRED 16           // number of 256-blocks summed

// Scratch: reduced operands (tf32-rounded, stored as fp32 bit patterns)
__device__ float g_xs[H * KRED];      // xs[m][k], row-major, 4 MB
__device__ float g_wsT[OUTF * KRED];  // wsT[n][k], row-major, 4 MB

__device__ __forceinline__ float to_tf32(float x) {
    float r;
    asm("cvt.rna.tf32.f32 %0, %1;" : "=f"(r) : "f"(x));
    return r;
}

// xs[m][t] = sum_v x[m][v*256 + t], rounded to tf32.
// One block per row m; 256 threads; every load/store fully coalesced.
__global__ void lin_reduce_x(const float* __restrict__ x) {
    const int m = blockIdx.x;
    const int t = threadIdx.x;
    const float* row = x + (size_t)m * INF;
    float acc = 0.f;
#pragma unroll
    for (int v = 0; v < NRED; v++) acc += row[v * KRED + t];
    g_xs[m * KRED + t] = to_tf32(acc);
}

// wsT[o][t] = sum_i weight[o][i*256 + t], rounded to tf32.
__global__ void lin_reduce_w(const float* __restrict__ w) {
    const int o = blockIdx.x;
    const int t = threadIdx.x;
    const float* row = w + (size_t)o * INF;
    float acc = 0.f;
#pragma unroll
    for (int i = 0; i < NRED; i++) acc += row[i * KRED + t];
    g_wsT[o * KRED + t] = to_tf32(acc);
}

// tf32 mma m16n8k8, D += A*B (fp32 accumulate)
__device__ __forceinline__ void mma_tf32(float* d, const uint32_t* a, const uint32_t* b) {
    asm volatile(
        "mma.sync.aligned.m16n8k8.row.col.f32.tf32.tf32.f32 "
        "{%0,%1,%2,%3}, {%4,%5,%6,%7}, {%8,%9}, {%0,%1,%2,%3};\n"
        : "+f"(d[0]), "+f"(d[1]), "+f"(d[2]), "+f"(d[3])
        : "r"(a[0]), "r"(a[1]), "r"(a[2]), "r"(a[3]),
          "r"(b[0]), "r"(b[1]));
}

// GEMM: out[4096][4096] = g_xs (4096x256) @ g_wsT^T (256x4096) + bias
// CTA tile 128x128, K chunked by 32 through shared memory.
// 8 warps: warp grid 4 (M) x 2 (N); warp tile 32x64 = 2 m16-tiles x 8 n8-tiles.
#define BM 128
#define BN 128
#define KC 32

__global__ void __launch_bounds__(256, 1)
lin_gemm_tf32(const float* __restrict__ bias, float* __restrict__ out) {
    __shared__ float As[BM][KC + 1];   // [row m][k], pad to kill conflicts
    __shared__ float Bs[BN][KC + 1];   // [row n][k]

    const int tid = threadIdx.x;
    const int warp = tid >> 5;
    const int lane = tid & 31;
    const int wm = warp >> 1;          // 0..3  -> 32-row slab
    const int wn = warp & 1;           // 0..1  -> 64-col slab
    const int g = lane >> 2;           // groupID
    const int t = lane & 3;            // threadID_in_group

    const int m0 = blockIdx.y * BM;
    const int n0 = blockIdx.x * BN;

    float acc[2][8][4];
#pragma unroll
    for (int mt = 0; mt < 2; mt++)
#pragma unroll
        for (int nt = 0; nt < 8; nt++)
#pragma unroll
            for (int i = 0; i < 4; i++) acc[mt][nt][i] = 0.f;

    for (int kc = 0; kc < KRED; kc += KC) {
        // Cooperative loads: 128x32 floats each = 1024 float4, 4 per thread.
#pragma unroll
        for (int r = 0; r < 4; r++) {
            int j = tid + 256 * r;
            int row = j >> 3;          // 8 float4 per row
            int c4 = (j & 7) * 4;
            float4 va = *(const float4*)&g_xs[(size_t)(m0 + row) * KRED + kc + c4];
            As[row][c4 + 0] = va.x; As[row][c4 + 1] = va.y;
            As[row][c4 + 2] = va.z; As[row][c4 + 3] = va.w;
            float4 vb = *(const float4*)&g_wsT[(size_t)(n0 + row) * KRED + kc + c4];
            Bs[row][c4 + 0] = vb.x; Bs[row][c4 + 1] = vb.y;
            Bs[row][c4 + 2] = vb.z; Bs[row][c4 + 3] = vb.w;
        }
        __syncthreads();

#pragma unroll
        for (int k8 = 0; k8 < KC / 8; k8++) {
            const int kk = k8 * 8;
            uint32_t a[2][4], b[8][2];
#pragma unroll
            for (int mt = 0; mt < 2; mt++) {
                int r = wm * 32 + mt * 16;
                a[mt][0] = __float_as_uint(As[r + g][kk + t]);
                a[mt][1] = __float_as_uint(As[r + g + 8][kk + t]);
                a[mt][2] = __float_as_uint(As[r + g][kk + t + 4]);
                a[mt][3] = __float_as_uint(As[r + g + 8][kk + t + 4]);
            }
#pragma unroll
            for (int nt = 0; nt < 8; nt++) {
                int c = wn * 64 + nt * 8;
                b[nt][0] = __float_as_uint(Bs[c + g][kk + t]);
                b[nt][1] = __float_as_uint(Bs[c + g][kk + t + 4]);
            }
#pragma unroll
            for (int mt = 0; mt < 2; mt++)
#pragma unroll
                for (int nt = 0; nt < 8; nt++)
                    mma_tf32(acc[mt][nt], a[mt], b[nt]);
        }
        __syncthreads();
    }

    // Epilogue: bias add + float2 stores.
#pragma unroll
    for (int mt = 0; mt < 2; mt++) {
        int row = m0 + wm * 32 + mt * 16 + g;
#pragma unroll
        for (int nt = 0; nt < 8; nt++) {
            int col = n0 + wn * 64 + nt * 8 + 2 * t;
            float b0 = bias[col], b1 = bias[col + 1];
            float2 v0 = make_float2(acc[mt][nt][0] + b0, acc[mt][nt][1] + b1);
            float2 v1 = make_float2(acc[mt][nt][2] + b0, acc[mt][nt][3] + b1);
            *(float2*)&out[(size_t)row * OUTF + col] = v0;
            *(float2*)&out[(size_t)(row + 8) * OUTF + col] = v1;
        }
    }
}

extern "C" void kernel_launch(void* const* d_in, const int* in_sizes, int n_in,
                              void* d_out, int out_size) {
    const float* x = (const float*)d_in[0];       // (4096, 4096)
    const float* w = (const float*)d_in[1];       // (4096, 4096)
    const float* bias = (const float*)d_in[2];    // (4096,)
    float* out = (float*)d_out;                   // (4096, 4096)

    lin_reduce_x<<<H, KRED>>>(x);
    lin_reduce_w<<<OUTF, KRED>>>(w);
    dim3 grid(OUTF / BN, H / BM);
    lin_gemm_tf32<<<grid, 256>>>(bias, out);
}

// round 3
// speedup vs baseline: 2.7417x; 2.7417x over previous
#include <cuda_runtime.h>
#include <cstdint>

#define H 4096
#define INF 4096
#define OUTF 4096
#define KRED 256
#define NRED 16

// Reduced operands (tf32-rounded fp32), 4 MB each -> L2-resident.
__device__ float g_xs[H * KRED];      // xs[m][k] row-major
__device__ float g_wsT[OUTF * KRED];  // wsT[n][k] row-major

__device__ __forceinline__ float to_tf32(float x) {
    float r;
    asm("cvt.rna.tf32.f32 %0, %1;" : "=f"(r) : "f"(x));
    return r;
}

// ---------------------------------------------------------------------------
// Fused reduction: blocks [0,1024) reduce x -> g_xs, [1024,2048) w -> g_wsT.
// 4 rows per block, 64 threads per row, all LDG.128 coalesced.
// ---------------------------------------------------------------------------
__global__ void __launch_bounds__(256) lin_reduce(const float* __restrict__ x,
                                                  const float* __restrict__ w) {
    int b = blockIdx.x;
    const float* src;
    float* dst;
    if (b < 1024) { src = x; dst = g_xs; }
    else          { src = w; dst = g_wsT; b -= 1024; }
    const int row = b * 4 + (threadIdx.x >> 6);
    const int p = (threadIdx.x & 63) * 4;
    const float4* s = (const float4*)(src + (size_t)row * INF + p);
    float4 a = make_float4(0.f, 0.f, 0.f, 0.f);
#pragma unroll
    for (int v = 0; v < NRED; v++) {
        float4 t = s[v * (KRED / 4)];
        a.x += t.x; a.y += t.y; a.z += t.z; a.w += t.w;
    }
    a.x = to_tf32(a.x); a.y = to_tf32(a.y); a.z = to_tf32(a.z); a.w = to_tf32(a.w);
    *(float4*)(dst + (size_t)row * KRED + p) = a;
}

// ---------------------------------------------------------------------------
// GEMM via mma.sync tf32: out = g_xs(4096x256) @ g_wsT^T(256x4096) + bias
// CTA tile 256(M) x 128(N); 8 warps in 4x2 grid; warp tile 64x64.
// cp.async double-buffered K-chunks of 32.
// ---------------------------------------------------------------------------
#define BM 256
#define BN 128
#define KC 32
#define LDSTR 36                       // smem row stride in floats (16B aligned, conflict-free)
#define A_BUF (BM * LDSTR)             // 9216 floats
#define B_BUF (BN * LDSTR)             // 4608 floats
#define SMEM_FLOATS (2 * A_BUF + 2 * B_BUF + 128)
#define SMEM_BYTES (SMEM_FLOATS * 4)   // 111104 B

__device__ __forceinline__ void mma_tf32(float* d, const uint32_t* a, const uint32_t* b) {
    asm volatile(
        "mma.sync.aligned.m16n8k8.row.col.f32.tf32.tf32.f32 "
        "{%0,%1,%2,%3}, {%4,%5,%6,%7}, {%8,%9}, {%0,%1,%2,%3};\n"
        : "+f"(d[0]), "+f"(d[1]), "+f"(d[2]), "+f"(d[3])
        : "r"(a[0]), "r"(a[1]), "r"(a[2]), "r"(a[3]),
          "r"(b[0]), "r"(b[1]));
}

__device__ __forceinline__ void cp16(uint32_t dst, const float* src) {
    asm volatile("cp.async.cg.shared.global [%0], [%1], 16;"
                 :: "r"(dst), "l"(src) : "memory");
}

__global__ void __launch_bounds__(256, 1)
lin_gemm(const float* __restrict__ bias, float* __restrict__ out) {
    extern __shared__ float sm[];
    float* AsBuf[2] = { sm, sm + A_BUF };
    float* BsBuf[2] = { sm + 2 * A_BUF, sm + 2 * A_BUF + B_BUF };
    float* s_bias = sm + 2 * A_BUF + 2 * B_BUF;

    const int tid = threadIdx.x;
    const int warp = tid >> 5;
    const int lane = tid & 31;
    const int wm = warp >> 1;            // 0..3 -> 64-row slab
    const int wn = warp & 1;             // 0..1 -> 64-col slab
    const int g = lane >> 2;
    const int t = lane & 3;
    const int m0 = blockIdx.y * BM;
    const int n0 = blockIdx.x * BN;

    if (tid < 128) s_bias[tid] = bias[n0 + tid];

    // cooperative-load coordinates (8 float4 per 32-float row chunk)
    const int lrow = tid >> 3;           // 0..31 base row (stride 32)
    const int lc4 = (tid & 7) * 4;       // k offset 0..28

    uint32_t aDst[2], bDst[2];
#pragma unroll
    for (int bf = 0; bf < 2; bf++) {
        aDst[bf] = (uint32_t)__cvta_generic_to_shared(AsBuf[bf] + lrow * LDSTR + lc4);
        bDst[bf] = (uint32_t)__cvta_generic_to_shared(BsBuf[bf] + lrow * LDSTR + lc4);
    }
    const float* aSrcBase = g_xs + (size_t)(m0 + lrow) * KRED + lc4;
    const float* bSrcBase = g_wsT + (size_t)(n0 + lrow) * KRED + lc4;

    float acc[4][8][4];
#pragma unroll
    for (int mt = 0; mt < 4; mt++)
#pragma unroll
        for (int nt = 0; nt < 8; nt++)
#pragma unroll
            for (int i = 0; i < 4; i++) acc[mt][nt][i] = 0.f;

    // prefetch chunk 0 into buffer 0
#pragma unroll
    for (int r = 0; r < 8; r++)        // A: rows lrow + 32r
        cp16(aDst[0] + r * 32 * LDSTR * 4, aSrcBase + (size_t)r * 32 * KRED);
#pragma unroll
    for (int r = 0; r < 4; r++)        // B: rows lrow + 32r
        cp16(bDst[0] + r * 32 * LDSTR * 4, bSrcBase + (size_t)r * 32 * KRED);
    asm volatile("cp.async.commit_group;" ::: "memory");

#pragma unroll
    for (int c = 0; c < 8; c++) {
        const int cur = c & 1;
        if (c < 7) {
            const int nxt = cur ^ 1;
            const int kc = (c + 1) * KC;
#pragma unroll
            for (int r = 0; r < 8; r++)
                cp16(aDst[nxt] + r * 32 * LDSTR * 4, aSrcBase + (size_t)r * 32 * KRED + kc);
#pragma unroll
            for (int r = 0; r < 4; r++)
                cp16(bDst[nxt] + r * 32 * LDSTR * 4, bSrcBase + (size_t)r * 32 * KRED + kc);
            asm volatile("cp.async.commit_group;" ::: "memory");
            asm volatile("cp.async.wait_group 1;" ::: "memory");
        } else {
            asm volatile("cp.async.wait_group 0;" ::: "memory");
        }
        __syncthreads();

        const float* Ab = AsBuf[cur] + (wm * 64 + g) * LDSTR + t;
        const float* Bb = BsBuf[cur] + (wn * 64 + g) * LDSTR + t;
#pragma unroll
        for (int k8 = 0; k8 < 4; k8++) {
            const int kk = k8 * 8;
            uint32_t a[4][4], b[8][2];
#pragma unroll
            for (int mt = 0; mt < 4; mt++) {
                const float* p = Ab + mt * 16 * LDSTR + kk;
                a[mt][0] = __float_as_uint(p[0]);
                a[mt][1] = __float_as_uint(p[8 * LDSTR]);
                a[mt][2] = __float_as_uint(p[4]);
                a[mt][3] = __float_as_uint(p[8 * LDSTR + 4]);
            }
#pragma unroll
            for (int nt = 0; nt < 8; nt++) {
                const float* p = Bb + nt * 8 * LDSTR + kk;
                b[nt][0] = __float_as_uint(p[0]);
                b[nt][1] = __float_as_uint(p[4]);
            }
#pragma unroll
            for (int mt = 0; mt < 4; mt++)
#pragma unroll
                for (int nt = 0; nt < 8; nt++)
                    mma_tf32(acc[mt][nt], a[mt], b[nt]);
        }
        __syncthreads();
    }

    // Epilogue: bias add + float2 stores
#pragma unroll
    for (int mt = 0; mt < 4; mt++) {
        const int r0 = m0 + wm * 64 + mt * 16 + g;
#pragma unroll
        for (int nt = 0; nt < 8; nt++) {
            const int col = wn * 64 + nt * 8 + 2 * t;
            const float b0 = s_bias[col], b1 = s_bias[col + 1];
            float2 v0 = make_float2(acc[mt][nt][0] + b0, acc[mt][nt][1] + b1);
            float2 v1 = make_float2(acc[mt][nt][2] + b0, acc[mt][nt][3] + b1);
            *(float2*)&out[(size_t)r0 * OUTF + n0 + col] = v0;
            *(float2*)&out[(size_t)(r0 + 8) * OUTF + n0 + col] = v1;
        }
    }
}

extern "C" void kernel_launch(void* const* d_in, const int* in_sizes, int n_in,
                              void* d_out, int out_size) {
    const float* x = (const float*)d_in[0];
    const float* w = (const float*)d_in[1];
    const float* bias = (const float*)d_in[2];
    float* out = (float*)d_out;

    cudaFuncSetAttribute(lin_gemm, cudaFuncAttributeMaxDynamicSharedMemorySize, SMEM_BYTES);

    lin_reduce<<<2048, 256>>>(x, w);
    dim3 grid(OUTF / BN, H / BM);   // (32, 16)
    lin_gemm<<<grid, 256, SMEM_BYTES>>>(bias, out);
}

// round 4
// speedup vs baseline: 2.8047x; 1.0230x over previous
#include <cuda_runtime.h>
#include <cstdint>

#define H 4096
#define INF 4096
#define OUTF 4096
#define KRED 256
#define NRED 16

// Reduced operands (tf32-rounded fp32) in k-PERMUTED layout:
// within each 8-col group, smem/global position 2*(k&3)+((k>>2)&1) holds col k.
__device__ float g_xs[H * KRED];
__device__ float g_wsT[OUTF * KRED];

__device__ __forceinline__ float to_tf32(float x) {
    float r;
    asm("cvt.rna.tf32.f32 %0, %1;" : "=f"(r) : "f"(x));
    return r;
}

// ---------------------------------------------------------------------------
// Fused reduction with permuted stores.
// blocks [0,1024): x -> g_xs ; [1024,2048): w -> g_wsT.
// 4 rows/block, 64 threads/row, float4 loads, scalar permuted stores.
// ---------------------------------------------------------------------------
__global__ void __launch_bounds__(256) lin_reduce(const float* __restrict__ x,
                                                  const float* __restrict__ w) {
    int b = blockIdx.x;
    const float* src;
    float* dst;
    if (b < 1024) { src = x; dst = g_xs; }
    else          { src = w; dst = g_wsT; b -= 1024; }
    const int row = b * 4 + (threadIdx.x >> 6);
    const int p = (threadIdx.x & 63) * 4;        // original k base (mult of 4)
    const float4* s = (const float4*)(src + (size_t)row * INF + p);
    float4 a = make_float4(0.f, 0.f, 0.f, 0.f);
#pragma unroll
    for (int v = 0; v < NRED; v++) {
        float4 t = s[v * (KRED / 4)];
        a.x += t.x; a.y += t.y; a.z += t.z; a.w += t.w;
    }
    // permuted positions: base + {0,2,4,6}
    float* d = dst + (size_t)row * KRED + (p & ~7) + ((p & 4) ? 1 : 0);
    d[0] = to_tf32(a.x);
    d[2] = to_tf32(a.y);
    d[4] = to_tf32(a.z);
    d[6] = to_tf32(a.w);
}

// ---------------------------------------------------------------------------
// GEMM via mma.sync tf32: out = xs(4096x256) @ wsT^T + bias
// CTA 256(M) x 128(N); 8 warps 4x2; warp tile 64x64.
// 3-stage cp.async pipeline, KC=32, one __syncthreads per chunk.
// ---------------------------------------------------------------------------
#define BM 256
#define BN 128
#define KC 32
#define LDSTR 40                        // floats; 40 % 32 == 8 -> conflict-free LDS.64
#define A_BUF (BM * LDSTR)              // 10240 floats
#define B_BUF (BN * LDSTR)              // 5120 floats
#define STAGE_F (A_BUF + B_BUF)         // 15360 floats per stage
#define SMEM_FLOATS (3 * STAGE_F + 128)
#define SMEM_BYTES (SMEM_FLOATS * 4)    // 185856 B

__device__ __forceinline__ void mma_tf32(float* d, const uint32_t* a, const uint32_t* b) {
    asm volatile(
        "mma.sync.aligned.m16n8k8.row.col.f32.tf32.tf32.f32 "
        "{%0,%1,%2,%3}, {%4,%5,%6,%7}, {%8,%9}, {%0,%1,%2,%3};\n"
        : "+f"(d[0]), "+f"(d[1]), "+f"(d[2]), "+f"(d[3])
        : "r"(a[0]), "r"(a[1]), "r"(a[2]), "r"(a[3]),
          "r"(b[0]), "r"(b[1]));
}

__device__ __forceinline__ void cp16(uint32_t dst, const float* src) {
    asm volatile("cp.async.cg.shared.global [%0], [%1], 16;"
                 :: "r"(dst), "l"(src) : "memory");
}

__global__ void __launch_bounds__(256, 1)
lin_gemm(const float* __restrict__ bias, float* __restrict__ out) {
    extern __shared__ float sm[];
    float* s_bias = sm + 3 * STAGE_F;

    const int tid = threadIdx.x;
    const int warp = tid >> 5;
    const int lane = tid & 31;
    const int wm = warp >> 1;            // 0..3 -> 64-row slab
    const int wn = warp & 1;             // 0..1 -> 64-col slab
    const int g = lane >> 2;
    const int t = lane & 3;
    const int m0 = blockIdx.y * BM;
    const int n0 = blockIdx.x * BN;

    if (tid < 128) s_bias[tid] = bias[n0 + tid];

    // cooperative-load coords: 8 float4 per 32-float chunk row
    const int lrow = tid >> 3;           // 0..31
    const int lc4 = (tid & 7) * 4;       // 0..28

    const uint32_t smem0 = (uint32_t)__cvta_generic_to_shared(sm);
    const uint32_t aDst0 = smem0 + (lrow * LDSTR + lc4) * 4;
    const uint32_t bDst0 = smem0 + (A_BUF + lrow * LDSTR + lc4) * 4;
    const float* aSrc = g_xs + (size_t)(m0 + lrow) * KRED + lc4;
    const float* bSrc = g_wsT + (size_t)(n0 + lrow) * KRED + lc4;

    float acc[4][8][4];
#pragma unroll
    for (int mt = 0; mt < 4; mt++)
#pragma unroll
        for (int nt = 0; nt < 8; nt++)
#pragma unroll
            for (int i = 0; i < 4; i++) acc[mt][nt][i] = 0.f;

    // prefetch chunks 0 and 1 into stages 0 and 1
#pragma unroll
    for (int pc = 0; pc < 2; pc++) {
        const uint32_t so = pc * STAGE_F * 4;
        const int kc = pc * KC;
#pragma unroll
        for (int r = 0; r < 8; r++)
            cp16(aDst0 + so + r * 32 * LDSTR * 4, aSrc + (size_t)r * 32 * KRED + kc);
#pragma unroll
        for (int r = 0; r < 4; r++)
            cp16(bDst0 + so + r * 32 * LDSTR * 4, bSrc + (size_t)r * 32 * KRED + kc);
        asm volatile("cp.async.commit_group;" ::: "memory");
    }

#pragma unroll
    for (int c = 0; c < 8; c++) {
        if (c < 7) asm volatile("cp.async.wait_group 1;" ::: "memory");
        else       asm volatile("cp.async.wait_group 0;" ::: "memory");
        __syncthreads();

        if (c < 6) {
            const int ns = (c + 2) % 3;
            const uint32_t so = ns * STAGE_F * 4;
            const int kc = (c + 2) * KC;
#pragma unroll
            for (int r = 0; r < 8; r++)
                cp16(aDst0 + so + r * 32 * LDSTR * 4, aSrc + (size_t)r * 32 * KRED + kc);
#pragma unroll
            for (int r = 0; r < 4; r++)
                cp16(bDst0 + so + r * 32 * LDSTR * 4, bSrc + (size_t)r * 32 * KRED + kc);
            asm volatile("cp.async.commit_group;" ::: "memory");
        }

        const float* As = sm + (c % 3) * STAGE_F;
        const float* Bs = As + A_BUF;
        const float* Ab = As + (wm * 64 + g) * LDSTR + 2 * t;
        const float* Bb = Bs + (wn * 64 + g) * LDSTR + 2 * t;

#pragma unroll
        for (int k8 = 0; k8 < 4; k8++) {
            const int kk = k8 * 8;
            uint32_t a[4][4], b[8][2];
#pragma unroll
            for (int mt = 0; mt < 4; mt++) {
                float2 lo = *(const float2*)(Ab + mt * 16 * LDSTR + kk);
                float2 hi = *(const float2*)(Ab + mt * 16 * LDSTR + 8 * LDSTR + kk);
                a[mt][0] = __float_as_uint(lo.x);
                a[mt][1] = __float_as_uint(hi.x);
                a[mt][2] = __float_as_uint(lo.y);
                a[mt][3] = __float_as_uint(hi.y);
            }
#pragma unroll
            for (int nt = 0; nt < 8; nt++) {
                float2 bb = *(const float2*)(Bb + nt * 8 * LDSTR + kk);
                b[nt][0] = __float_as_uint(bb.x);
                b[nt][1] = __float_as_uint(bb.y);
            }
#pragma unroll
            for (int mt = 0; mt < 4; mt++)
#pragma unroll
                for (int nt = 0; nt < 8; nt++)
                    mma_tf32(acc[mt][nt], a[mt], b[nt]);
        }
    }

    // Epilogue: bias + float2 stores
#pragma unroll
    for (int mt = 0; mt < 4; mt++) {
        const int r0 = m0 + wm * 64 + mt * 16 + g;
#pragma unroll
        for (int nt = 0; nt < 8; nt++) {
            const int col = wn * 64 + nt * 8 + 2 * t;
            const float b0 = s_bias[col], b1 = s_bias[col + 1];
            float2 v0 = make_float2(acc[mt][nt][0] + b0, acc[mt][nt][1] + b1);
            float2 v1 = make_float2(acc[mt][nt][2] + b0, acc[mt][nt][3] + b1);
            *(float2*)&out[(size_t)r0 * OUTF + n0 + col] = v0;
            *(float2*)&out[(size_t)(r0 + 8) * OUTF + n0 + col] = v1;
        }
    }
}

extern "C" void kernel_launch(void* const* d_in, const int* in_sizes, int n_in,
                              void* d_out, int out_size) {
    const float* x = (const float*)d_in[0];
    const float* w = (const float*)d_in[1];
    const float* bias = (const float*)d_in[2];
    float* out = (float*)d_out;

    cudaFuncSetAttribute(lin_gemm, cudaFuncAttributeMaxDynamicSharedMemorySize, SMEM_BYTES);

    lin_reduce<<<2048, 256>>>(x, w);
    dim3 grid(OUTF / BN, H / BM);   // (32, 16)
    lin_gemm<<<grid, 256, SMEM_BYTES>>>(bias, out);
}